// round 1
// baseline (speedup 1.0000x reference)
#include <cuda_runtime.h>

#define H      128
#define W      128
#define NLAM   128
#define BATCH  16
#define NK     4
#define HP     192
#define WP     192

// scratch accumulator: (B*NK, HP, WP) = 9.4 MB
__device__ float g_acc[BATCH * NK * HP * WP];

// ---------------------------------------------------------------------------
// Kernel 1: per-(b,k) accumulate over wavelengths of uniformly-shifted slices.
// Block: 16x16 threads, each thread owns a 4x4 output micro-tile -> 64x64 tile.
// Grid: (3, 3, B*NK).
// ---------------------------------------------------------------------------
__global__ __launch_bounds__(256) void accum_kernel(
    const float* __restrict__ cube,   // (B, NLAM, H, W)
    const float* __restrict__ dx,     // (NK, NLAM)
    const float* __restrict__ dy)     // (NK, NLAM)
{
    __shared__ int   s_nx[NLAM];
    __shared__ int   s_ny[NLAM];
    __shared__ float s_w[NLAM][4];    // w00=fy*fx, w01=fy*gx, w10=gy*fx, w11=gy*gx

    const int bz = blockIdx.z;
    const int b  = bz >> 2;
    const int k  = bz & 3;

    const int tid = threadIdx.y * 16 + threadIdx.x;
    if (tid < NLAM) {
        float dxv = dx[k * NLAM + tid];
        float dyv = dy[k * NLAM + tid];
        float nxf = floorf(dxv), nyf = floorf(dyv);
        float fx = dxv - nxf, fy = dyv - nyf;
        float gx = 1.0f - fx, gy = 1.0f - fy;
        s_nx[tid] = (int)nxf;
        s_ny[tid] = (int)nyf;
        s_w[tid][0] = fy * fx;
        s_w[tid][1] = fy * gx;
        s_w[tid][2] = gy * fx;
        s_w[tid][3] = gy * gx;
    }
    __syncthreads();

    const int tx0 = blockIdx.x * 64 + threadIdx.x * 4;
    const int ty0 = blockIdx.y * 64 + threadIdx.y * 4;

    float acc[4][4] = {};

    const float* cb = cube + (size_t)b * NLAM * H * W;

    for (int l = 0; l < NLAM; ++l) {
        const int nx = s_nx[l];
        const int ny = s_ny[l];
        // this thread needs cube rows [br, br+4], cols [bc, bc+4]
        const int br = ty0 - 33 - ny;
        const int bc = tx0 - 33 - nx;
        // fully out of bounds -> contributes exactly zero
        if (br > H - 1 || br < -4 || bc > W - 1 || bc < -4) continue;

        const float w00 = s_w[l][0];
        const float w01 = s_w[l][1];
        const float w10 = s_w[l][2];
        const float w11 = s_w[l][3];
        const float* sl = cb + l * H * W;

        const bool interior = (br >= 0) & (br <= H - 5) & (bc >= 0) & (bc <= W - 5);

        float v[5][5];

        if (w00 == 0.0f && w01 == 0.0f) {
            // fy == 0 exactly (k=0 and lambda=0 cases): only rows v[1..4] needed
            if (interior) {
                #pragma unroll
                for (int i = 1; i < 5; ++i) {
                    const float* rp = sl + (br + i) * W + bc;
                    #pragma unroll
                    for (int j = 0; j < 5; ++j) v[i][j] = __ldg(rp + j);
                }
            } else {
                #pragma unroll
                for (int i = 1; i < 5; ++i) {
                    int r = br + i;
                    bool rok = ((unsigned)r < (unsigned)H);
                    const float* rp = sl + r * W;
                    #pragma unroll
                    for (int j = 0; j < 5; ++j) {
                        int c = bc + j;
                        v[i][j] = (rok && ((unsigned)c < (unsigned)W)) ? __ldg(rp + c) : 0.0f;
                    }
                }
            }
            #pragma unroll
            for (int i = 0; i < 4; ++i)
                #pragma unroll
                for (int j = 0; j < 4; ++j) {
                    acc[i][j] += w10 * v[i + 1][j];
                    acc[i][j] += w11 * v[i + 1][j + 1];
                }
        } else {
            if (interior) {
                #pragma unroll
                for (int i = 0; i < 5; ++i) {
                    const float* rp = sl + (br + i) * W + bc;
                    #pragma unroll
                    for (int j = 0; j < 5; ++j) v[i][j] = __ldg(rp + j);
                }
            } else {
                #pragma unroll
                for (int i = 0; i < 5; ++i) {
                    int r = br + i;
                    bool rok = ((unsigned)r < (unsigned)H);
                    const float* rp = sl + r * W;
                    #pragma unroll
                    for (int j = 0; j < 5; ++j) {
                        int c = bc + j;
                        v[i][j] = (rok && ((unsigned)c < (unsigned)W)) ? __ldg(rp + c) : 0.0f;
                    }
                }
            }
            #pragma unroll
            for (int i = 0; i < 4; ++i)
                #pragma unroll
                for (int j = 0; j < 4; ++j) {
                    acc[i][j] += w00 * v[i][j];
                    acc[i][j] += w01 * v[i][j + 1];
                    acc[i][j] += w10 * v[i + 1][j];
                    acc[i][j] += w11 * v[i + 1][j + 1];
                }
        }
    }

    float* ap = g_acc + ((size_t)bz * HP + ty0) * WP + tx0;
    #pragma unroll
    for (int i = 0; i < 4; ++i)
        #pragma unroll
        for (int j = 0; j < 4; ++j)
            ap[i * WP + j] = acc[i][j];
}

// ---------------------------------------------------------------------------
// Kernel 2: 7x7 PSF convolution (same padding, zeros), acc -> out.
// Block: (32, 8), output tile 32x32 (each thread 4 consecutive rows).
// Grid: (6, 6, B*NK).
// ---------------------------------------------------------------------------
__global__ __launch_bounds__(256) void conv_kernel(
    const float* __restrict__ psf,    // (7,7)
    float* __restrict__ out)          // (B, NK, HP, WP)
{
    __shared__ float s[38 * 40];
    __shared__ float sp[49];

    const int bz = blockIdx.z;
    const float* ap = g_acc + (size_t)bz * HP * WP;

    const int tid = threadIdx.y * 32 + threadIdx.x;
    if (tid < 49) sp[tid] = psf[tid];

    const int x0 = blockIdx.x * 32;
    const int y0 = blockIdx.y * 32;

    for (int i = tid; i < 38 * 38; i += 256) {
        int r = i / 38, c = i % 38;
        int gy = y0 + r - 3;
        int gx = x0 + c - 3;
        s[r * 40 + c] = (((unsigned)gy < (unsigned)HP) && ((unsigned)gx < (unsigned)WP))
                            ? ap[gy * WP + gx] : 0.0f;
    }
    __syncthreads();

    float w[49];
    #pragma unroll
    for (int i = 0; i < 49; ++i) w[i] = sp[i];

    const int tx = threadIdx.x;
    const int rbase = threadIdx.y * 4;

    float a0 = 0.f, a1 = 0.f, a2 = 0.f, a3 = 0.f;
    #pragma unroll
    for (int rr = 0; rr < 10; ++rr) {
        #pragma unroll
        for (int v = 0; v < 7; ++v) {
            float xv = s[(rbase + rr) * 40 + tx + v];
            if (rr <= 6)            a0 += w[rr * 7 + v] * xv;
            if (rr >= 1 && rr <= 7) a1 += w[(rr - 1) * 7 + v] * xv;
            if (rr >= 2 && rr <= 8) a2 += w[(rr - 2) * 7 + v] * xv;
            if (rr >= 3)            a3 += w[(rr - 3) * 7 + v] * xv;
        }
    }

    float* op = out + ((size_t)bz * HP + y0 + rbase) * WP + x0 + tx;
    op[0 * WP] = a0;
    op[1 * WP] = a1;
    op[2 * WP] = a2;
    op[3 * WP] = a3;
}

extern "C" void kernel_launch(void* const* d_in, const int* in_sizes, int n_in,
                              void* d_out, int out_size)
{
    const float* cube = (const float*)d_in[0];
    const float* psf  = (const float*)d_in[1];
    const float* dx   = (const float*)d_in[2];
    const float* dy   = (const float*)d_in[3];
    float* out = (float*)d_out;

    dim3 gb(3, 3, BATCH * NK), tb(16, 16);
    accum_kernel<<<gb, tb>>>(cube, dx, dy);

    dim3 gc(6, 6, BATCH * NK), tc(32, 8);
    conv_kernel<<<gc, tc>>>(psf, out);
}